// round 1
// baseline (speedup 1.0000x reference)
#include <cuda_runtime.h>
#include <cuda_fp16.h>
#include <cstdint>

#define NPTS  2000000
#define TILES 15625          // 2,000,000 / 128 exactly

// dynamic shared layout (bytes)
#define XS_OFF 0             // half [128][120]   (stride 120 halfs, conflict-free)
#define W1_OFF 30720         // half [64][120]    W1S[j][k] = W1[k][j], k padded 105->112 (zeros)
#define W2_OFF 46080         // half [64][72]     W2S[j][k] = W2[k][j]
#define W3_OFF 55296         // float4 [64]       (W3 row k, padded)
#define B1_OFF 56320         // float [64]
#define B2_OFF 56576         // float [64]
#define B3_OFF 56832         // float [4]
#define SMEM_BYTES 56848

__device__ __forceinline__ uint32_t pk(float a, float b) {
    __half2 h = __floats2half2_rn(a, b);   // low = a, high = b
    return *reinterpret_cast<uint32_t*>(&h);
}

__device__ __forceinline__ void sts8(__half* p,
    float a, float b, float c, float d, float e, float f, float g, float h) {
    uint4 u;
    u.x = pk(a, b); u.y = pk(c, d); u.z = pk(e, f); u.w = pk(g, h);
    *reinterpret_cast<uint4*>(p) = u;      // 16B aligned: row base 240B, offsets 16B
}

// D = A(16x16,f16,row) * B(16x8,f16,col) + D,  fp32 accum
__device__ __forceinline__ void mma16816(float* c,
    uint32_t a0, uint32_t a1, uint32_t a2, uint32_t a3,
    uint32_t b0, uint32_t b1) {
    asm volatile(
        "mma.sync.aligned.m16n8k16.row.col.f32.f16.f16.f32 "
        "{%0,%1,%2,%3}, {%4,%5,%6,%7}, {%8,%9}, {%0,%1,%2,%3};\n"
        : "+f"(c[0]), "+f"(c[1]), "+f"(c[2]), "+f"(c[3])
        : "r"(a0), "r"(a1), "r"(a2), "r"(a3), "r"(b0), "r"(b1));
}

__global__ void __launch_bounds__(128)
fused_encode_mlp(const float* __restrict__ bases,
                 const float* __restrict__ normals,
                 const float* __restrict__ enc,
                 const float* __restrict__ W1, const float* __restrict__ b1,
                 const float* __restrict__ W2, const float* __restrict__ b2,
                 const float* __restrict__ W3, const float* __restrict__ b3,
                 float* __restrict__ out)
{
    extern __shared__ char smem[];
    __half*  XS  = reinterpret_cast<__half*>(smem + XS_OFF);
    __half*  W1S = reinterpret_cast<__half*>(smem + W1_OFF);
    __half*  W2S = reinterpret_cast<__half*>(smem + W2_OFF);
    float4*  W3S = reinterpret_cast<float4*>(smem + W3_OFF);
    float*   B1S = reinterpret_cast<float*>(smem + B1_OFF);
    float*   B2S = reinterpret_cast<float*>(smem + B2_OFF);
    float*   B3S = reinterpret_cast<float*>(smem + B3_OFF);

    const int tid  = threadIdx.x;
    const int lane = tid & 31;
    const int wp   = tid >> 5;
    const int g    = lane >> 2;      // groupID (row within 8)
    const int tig  = lane & 3;       // thread-in-group (col pair / k pair)
    const int warpRow = wp * 32;

    // ---- stage weights once per CTA ----
    for (int i = tid; i < 64 * 120; i += 128) W1S[i] = __float2half(0.f);  // zero incl. K-pad rows
    __syncthreads();
    for (int i = tid; i < 105 * 64; i += 128) {
        int k = i >> 6, j = i & 63;
        W1S[j * 120 + k] = __float2half(W1[i]);
    }
    for (int i = tid; i < 64 * 64; i += 128) {
        int k = i >> 6, j = i & 63;
        W2S[j * 72 + k] = __float2half(W2[i]);
    }
    if (tid < 64) {
        W3S[tid] = make_float4(W3[tid * 3 + 0], W3[tid * 3 + 1], W3[tid * 3 + 2], 0.f);
        B1S[tid] = b1[tid];
        B2S[tid] = b2[tid];
    }
    if (tid < 3) B3S[tid] = b3[tid];
    __syncthreads();

    const uint32_t* Xw  = reinterpret_cast<const uint32_t*>(XS);   // 60 words / row
    const uint32_t* W1w = reinterpret_cast<const uint32_t*>(W1S);  // 60 words / row
    const uint32_t* W2w = reinterpret_cast<const uint32_t*>(W2S);  // 36 words / row

    for (int tile = blockIdx.x; tile < TILES; tile += gridDim.x) {
        const int row = tile * 128 + tid;    // this thread's point (always valid)

        // ================= features -> SMEM (fp16, cols 0..111) =================
        __half* xr = XS + tid * 120;

        const float4* ep = reinterpret_cast<const float4*>(enc + (size_t)row * 20);
        float4 e0 = ep[0], e1 = ep[1], e2 = ep[2], e3 = ep[3], e4v = ep[4];
        sts8(xr + 0, e0.x, e0.y, e0.z, e0.w, e1.x, e1.y, e1.z, e1.w);
        sts8(xr + 8, e2.x, e2.y, e2.z, e2.w, e3.x, e3.y, e3.z, e3.w);

        float bx = bases[row * 3 + 0], by = bases[row * 3 + 1], bz = bases[row * 3 + 2];

        float sn[8][3], cs[8][3];
        {
            float fx = bx, fy = by, fz = bz;
            #pragma unroll
            for (int i = 0; i < 8; i++) {
                fx *= 2.f; fy *= 2.f; fz *= 2.f;     // 2^(i+1) * base
                __sincosf(fx, &sn[i][0], &cs[i][0]);
                __sincosf(fy, &sn[i][1], &cs[i][1]);
                __sincosf(fz, &sn[i][2], &cs[i][2]);
            }
        }
        sts8(xr + 16, e4v.x, e4v.y, e4v.z, e4v.w, bx, by, bz, sn[0][0]);
        sts8(xr + 24, sn[0][1], sn[0][2], cs[0][0], cs[0][1], cs[0][2], sn[1][0], sn[1][1], sn[1][2]);
        sts8(xr + 32, cs[1][0], cs[1][1], cs[1][2], sn[2][0], sn[2][1], sn[2][2], cs[2][0], cs[2][1]);
        sts8(xr + 40, cs[2][2], sn[3][0], sn[3][1], sn[3][2], cs[3][0], cs[3][1], cs[3][2], sn[4][0]);
        sts8(xr + 48, sn[4][1], sn[4][2], cs[4][0], cs[4][1], cs[4][2], sn[5][0], sn[5][1], sn[5][2]);
        sts8(xr + 56, cs[5][0], cs[5][1], cs[5][2], sn[6][0], sn[6][1], sn[6][2], cs[6][0], cs[6][1]);

        float n0 = normals[row * 2 + 0], n1 = normals[row * 2 + 1];
        sts8(xr + 64, cs[6][2], sn[7][0], sn[7][1], sn[7][2], cs[7][0], cs[7][1], cs[7][2], n0);

        float bl0[16], bl1[16];
        #pragma unroll
        for (int k = 0; k < 16; k++) {
            float T = (float)k * (1.f / 15.f);
            float d0 = n0 - T; bl0[k] = __expf(-50.f * d0 * d0);   // 1/(2*0.1^2) = 50
            float d1 = n1 - T; bl1[k] = __expf(-50.f * d1 * d1);
        }
        sts8(xr + 72,  n1, bl0[0], bl0[1], bl0[2], bl0[3], bl0[4], bl0[5], bl0[6]);
        sts8(xr + 80,  bl0[7], bl0[8], bl0[9], bl0[10], bl0[11], bl0[12], bl0[13], bl0[14]);
        sts8(xr + 88,  bl0[15], bl1[0], bl1[1], bl1[2], bl1[3], bl1[4], bl1[5], bl1[6]);
        sts8(xr + 96,  bl1[7], bl1[8], bl1[9], bl1[10], bl1[11], bl1[12], bl1[13], bl1[14]);
        sts8(xr + 104, bl1[15], 0.f, 0.f, 0.f, 0.f, 0.f, 0.f, 0.f);  // K-pad 105..111

        __syncwarp();   // warp reads only its own 32 rows

        // ================= layer 1: [32 x 112] @ [112 x 64], K=7 steps =================
        float acc[2][8][4];
        #pragma unroll
        for (int mt = 0; mt < 2; mt++)
            #pragma unroll
            for (int nt = 0; nt < 8; nt++)
                #pragma unroll
                for (int j = 0; j < 4; j++) acc[mt][nt][j] = 0.f;

        #pragma unroll
        for (int kk = 0; kk < 7; kk++) {
            uint32_t a[2][4];
            #pragma unroll
            for (int mt = 0; mt < 2; mt++) {
                int r = warpRow + mt * 16 + g;
                a[mt][0] = Xw[r * 60 + kk * 8 + tig];
                a[mt][1] = Xw[(r + 8) * 60 + kk * 8 + tig];
                a[mt][2] = Xw[r * 60 + kk * 8 + tig + 4];
                a[mt][3] = Xw[(r + 8) * 60 + kk * 8 + tig + 4];
            }
            #pragma unroll
            for (int nt = 0; nt < 8; nt++) {
                int n = nt * 8 + g;
                uint32_t bb0 = W1w[n * 60 + kk * 8 + tig];
                uint32_t bb1 = W1w[n * 60 + kk * 8 + tig + 4];
                mma16816(acc[0][nt], a[0][0], a[0][1], a[0][2], a[0][3], bb0, bb1);
                mma16816(acc[1][nt], a[1][0], a[1][1], a[1][2], a[1][3], bb0, bb1);
            }
        }

        // bias + sin + pack into layer-2 A fragments (C-frag layout == A-frag layout)
        uint32_t ah[2][8][2];
        #pragma unroll
        for (int mt = 0; mt < 2; mt++)
            #pragma unroll
            for (int nt = 0; nt < 8; nt++) {
                float bv0 = B1S[nt * 8 + tig * 2];
                float bv1 = B1S[nt * 8 + tig * 2 + 1];
                ah[mt][nt][0] = pk(__sinf(acc[mt][nt][0] + bv0), __sinf(acc[mt][nt][1] + bv1));
                ah[mt][nt][1] = pk(__sinf(acc[mt][nt][2] + bv0), __sinf(acc[mt][nt][3] + bv1));
            }

        // ================= layer 2: [32 x 64] @ [64 x 64], K=4 steps (A in regs) =================
        float ac2[2][8][4];
        #pragma unroll
        for (int mt = 0; mt < 2; mt++)
            #pragma unroll
            for (int nt = 0; nt < 8; nt++)
                #pragma unroll
                for (int j = 0; j < 4; j++) ac2[mt][nt][j] = 0.f;

        #pragma unroll
        for (int kk = 0; kk < 4; kk++) {
            #pragma unroll
            for (int nt = 0; nt < 8; nt++) {
                int n = nt * 8 + g;
                uint32_t bb0 = W2w[n * 36 + kk * 8 + tig];
                uint32_t bb1 = W2w[n * 36 + kk * 8 + tig + 4];
                #pragma unroll
                for (int mt = 0; mt < 2; mt++)
                    mma16816(ac2[mt][nt],
                             ah[mt][2 * kk][0], ah[mt][2 * kk][1],
                             ah[mt][2 * kk + 1][0], ah[mt][2 * kk + 1][1],
                             bb0, bb1);
            }
        }

        // bias + sin (in place)
        #pragma unroll
        for (int mt = 0; mt < 2; mt++)
            #pragma unroll
            for (int nt = 0; nt < 8; nt++) {
                float bv0 = B2S[nt * 8 + tig * 2];
                float bv1 = B2S[nt * 8 + tig * 2 + 1];
                ac2[mt][nt][0] = __sinf(ac2[mt][nt][0] + bv0);
                ac2[mt][nt][1] = __sinf(ac2[mt][nt][1] + bv1);
                ac2[mt][nt][2] = __sinf(ac2[mt][nt][2] + bv0);
                ac2[mt][nt][3] = __sinf(ac2[mt][nt][3] + bv1);
            }

        // ================= layer 3: [32 x 64] @ [64 x 3] + residual =================
        float b3x = B3S[0], b3y = B3S[1], b3z = B3S[2];
        #pragma unroll
        for (int mt = 0; mt < 2; mt++) {
            float pA0 = 0.f, pA1 = 0.f, pA2 = 0.f;   // row g
            float pB0 = 0.f, pB1 = 0.f, pB2 = 0.f;   // row g+8
            #pragma unroll
            for (int nt = 0; nt < 8; nt++) {
                #pragma unroll
                for (int p = 0; p < 2; p++) {
                    float4 w = W3S[nt * 8 + tig * 2 + p];
                    float vA = ac2[mt][nt][p];
                    float vB = ac2[mt][nt][2 + p];
                    pA0 += vA * w.x; pA1 += vA * w.y; pA2 += vA * w.z;
                    pB0 += vB * w.x; pB1 += vB * w.y; pB2 += vB * w.z;
                }
            }
            // reduce across the 4 lanes of the group (tig dimension)
            pA0 += __shfl_xor_sync(0xffffffffu, pA0, 1); pA0 += __shfl_xor_sync(0xffffffffu, pA0, 2);
            pA1 += __shfl_xor_sync(0xffffffffu, pA1, 1); pA1 += __shfl_xor_sync(0xffffffffu, pA1, 2);
            pA2 += __shfl_xor_sync(0xffffffffu, pA2, 1); pA2 += __shfl_xor_sync(0xffffffffu, pA2, 2);
            pB0 += __shfl_xor_sync(0xffffffffu, pB0, 1); pB0 += __shfl_xor_sync(0xffffffffu, pB0, 2);
            pB1 += __shfl_xor_sync(0xffffffffu, pB1, 1); pB1 += __shfl_xor_sync(0xffffffffu, pB1, 2);
            pB2 += __shfl_xor_sync(0xffffffffu, pB2, 1); pB2 += __shfl_xor_sync(0xffffffffu, pB2, 2);

            if (tig == 0) {
                int rA = tile * 128 + warpRow + mt * 16 + g;
                out[rA * 3 + 0] = bases[rA * 3 + 0] + pA0 + b3x;
                out[rA * 3 + 1] = bases[rA * 3 + 1] + pA1 + b3y;
                out[rA * 3 + 2] = bases[rA * 3 + 2] + pA2 + b3z;
                int rB = rA + 8;
                out[rB * 3 + 0] = bases[rB * 3 + 0] + pB0 + b3x;
                out[rB * 3 + 1] = bases[rB * 3 + 1] + pB1 + b3y;
                out[rB * 3 + 2] = bases[rB * 3 + 2] + pB2 + b3z;
            }
        }
        __syncwarp();   // all lanes done reading XS before next tile overwrites it
    }
}

extern "C" void kernel_launch(void* const* d_in, const int* in_sizes, int n_in,
                              void* d_out, int out_size) {
    const float* bases   = (const float*)d_in[0];
    const float* normals = (const float*)d_in[1];
    const float* enc     = (const float*)d_in[2];
    const float* W1      = (const float*)d_in[3];
    const float* b1      = (const float*)d_in[4];
    const float* W2      = (const float*)d_in[5];
    const float* b2      = (const float*)d_in[6];
    const float* W3      = (const float*)d_in[7];
    const float* b3      = (const float*)d_in[8];
    float* out = (float*)d_out;

    cudaFuncSetAttribute(fused_encode_mlp,
                         cudaFuncAttributeMaxDynamicSharedMemorySize, SMEM_BYTES);

    // persistent: 148 SMs x 4 CTAs (smem-limited occupancy)
    fused_encode_mlp<<<592, 128, SMEM_BYTES>>>(bases, normals, enc,
                                               W1, b1, W2, b2, W3, b3, out);
}

// round 2
// speedup vs baseline: 1.1083x; 1.1083x over previous
#include <cuda_runtime.h>
#include <cuda_fp16.h>
#include <cstdint>

#define NPTS  2000000
#define TILES 15625          // 2,000,000 / 128 exactly

// dynamic shared layout (bytes)
#define XS_OFF 0             // half [128][120]   (stride 120 halfs = 240B, conflict-free for LDSM)
#define W1_OFF 30720         // half [64][120]    W1S[j][k] = W1[k][j], k padded 105->112 (zeros)
#define W2_OFF 46080         // half [64][72]     W2S[j][k] = W2[k][j]
#define W3_OFF 55296         // float4 [64]       (W3 row k, padded)
#define B1_OFF 56320         // float [64]
#define B2_OFF 56576         // float [64]
#define B3_OFF 56832         // float [4]
#define SMEM_BYTES 56848

__device__ __forceinline__ uint32_t pk(float a, float b) {
    __half2 h = __floats2half2_rn(a, b);   // low = a, high = b
    return *reinterpret_cast<uint32_t*>(&h);
}

__device__ __forceinline__ void sts8(__half* p,
    float a, float b, float c, float d, float e, float f, float g, float h) {
    uint4 u;
    u.x = pk(a, b); u.y = pk(c, d); u.z = pk(e, f); u.w = pk(g, h);
    *reinterpret_cast<uint4*>(p) = u;      // 16B aligned: row base 240B, offsets 16B
}

// D = A(16x16,f16,row) * B(16x8,f16,col) + D,  fp32 accum
__device__ __forceinline__ void mma16816(float* c,
    uint32_t a0, uint32_t a1, uint32_t a2, uint32_t a3,
    uint32_t b0, uint32_t b1) {
    asm volatile(
        "mma.sync.aligned.m16n8k16.row.col.f32.f16.f16.f32 "
        "{%0,%1,%2,%3}, {%4,%5,%6,%7}, {%8,%9}, {%0,%1,%2,%3};\n"
        : "+f"(c[0]), "+f"(c[1]), "+f"(c[2]), "+f"(c[3])
        : "r"(a0), "r"(a1), "r"(a2), "r"(a3), "r"(b0), "r"(b1));
}

__device__ __forceinline__ void ldsm4(uint32_t* r, uint32_t addr) {
    asm volatile(
        "ldmatrix.sync.aligned.m8n8.x4.shared.b16 {%0,%1,%2,%3}, [%4];\n"
        : "=r"(r[0]), "=r"(r[1]), "=r"(r[2]), "=r"(r[3]) : "r"(addr));
}

__global__ void __launch_bounds__(128)
fused_encode_mlp(const float* __restrict__ bases,
                 const float* __restrict__ normals,
                 const float* __restrict__ enc,
                 const float* __restrict__ W1, const float* __restrict__ b1,
                 const float* __restrict__ W2, const float* __restrict__ b2,
                 const float* __restrict__ W3, const float* __restrict__ b3,
                 float* __restrict__ out)
{
    extern __shared__ char smem[];
    __half*  XS  = reinterpret_cast<__half*>(smem + XS_OFF);
    __half*  W1S = reinterpret_cast<__half*>(smem + W1_OFF);
    __half*  W2S = reinterpret_cast<__half*>(smem + W2_OFF);
    float4*  W3S = reinterpret_cast<float4*>(smem + W3_OFF);
    float*   B1S = reinterpret_cast<float*>(smem + B1_OFF);
    float*   B2S = reinterpret_cast<float*>(smem + B2_OFF);
    float*   B3S = reinterpret_cast<float*>(smem + B3_OFF);

    const int tid  = threadIdx.x;
    const int lane = tid & 31;
    const int wp   = tid >> 5;
    const int g    = lane >> 2;      // groupID (row within 8)
    const int tig  = lane & 3;       // thread-in-group
    const int warpRow = wp * 32;

    // ---- stage weights once per CTA ----
    for (int i = tid; i < 64 * 120; i += 128) W1S[i] = __float2half(0.f);  // zero incl. K-pad
    __syncthreads();
    for (int i = tid; i < 105 * 64; i += 128) {
        int k = i >> 6, j = i & 63;
        W1S[j * 120 + k] = __float2half(W1[i]);
    }
    for (int i = tid; i < 64 * 64; i += 128) {
        int k = i >> 6, j = i & 63;
        W2S[j * 72 + k] = __float2half(W2[i]);
    }
    if (tid < 64) {
        W3S[tid] = make_float4(W3[tid * 3 + 0], W3[tid * 3 + 1], W3[tid * 3 + 2], 0.f);
        B1S[tid] = b1[tid];
        B2S[tid] = b2[tid];
    }
    if (tid < 3) B3S[tid] = b3[tid];
    __syncthreads();

    // ---- precompute ldmatrix base addresses (byte offsets in shared space) ----
    const uint32_t xs_b  = (uint32_t)__cvta_generic_to_shared(XS);
    const uint32_t w1_b  = (uint32_t)__cvta_generic_to_shared(W1S);
    const uint32_t w2_b  = (uint32_t)__cvta_generic_to_shared(W2S);

    // A-tile (m16 x k16) x4 lanes mapping: m0 rows0-7/k0-7, m1 rows8-15/k0-7, m2 rows0-7/k8-15, m3 rows8-15/k8-15
    const int aRowIn = (lane & 7) + ((lane >> 3) & 1) * 8;
    const int aCol   = ((lane >> 4) & 1) * 16;
    uint32_t baseA0 = xs_b + (uint32_t)((warpRow + aRowIn) * 240 + aCol);
    uint32_t baseA1 = baseA0 + 16u * 240u;

    // B-pair (two n8 x k16 tiles) mapping: m0 ntA/k0-7, m1 ntA/k8-15, m2 ntB/k0-7, m3 ntB/k8-15
    const int bRowIn = (lane & 7) + ((lane >> 4) & 1) * 8;
    const int bCol   = ((lane >> 3) & 1) * 16;
    uint32_t baseB1[4], baseB2[4];
    #pragma unroll
    for (int p = 0; p < 4; p++) {
        baseB1[p] = w1_b + (uint32_t)((p * 16 + bRowIn) * 240 + bCol);
        baseB2[p] = w2_b + (uint32_t)((p * 16 + bRowIn) * 144 + bCol);
    }

    for (int tile = blockIdx.x; tile < TILES; tile += gridDim.x) {
        const int row = tile * 128 + tid;    // this thread's point (always valid)

        // ================= features -> SMEM (fp16, cols 0..111) =================
        __half* xr = XS + tid * 120;

        const float4* ep = reinterpret_cast<const float4*>(enc + (size_t)row * 20);
        float4 e0 = ep[0], e1 = ep[1], e2 = ep[2], e3 = ep[3], e4v = ep[4];
        sts8(xr + 0, e0.x, e0.y, e0.z, e0.w, e1.x, e1.y, e1.z, e1.w);
        sts8(xr + 8, e2.x, e2.y, e2.z, e2.w, e3.x, e3.y, e3.z, e3.w);

        float bx = bases[row * 3 + 0], by = bases[row * 3 + 1], bz = bases[row * 3 + 2];

        // posenc via double-angle recurrence: only one sincos per dim (MUFU 48 -> 6)
        float sn[8][3], cs[8][3];
        __sincosf(2.f * bx, &sn[0][0], &cs[0][0]);
        __sincosf(2.f * by, &sn[0][1], &cs[0][1]);
        __sincosf(2.f * bz, &sn[0][2], &cs[0][2]);
        #pragma unroll
        for (int i = 1; i < 8; i++) {
            #pragma unroll
            for (int d = 0; d < 3; d++) {
                float s = sn[i - 1][d], c = cs[i - 1][d];
                sn[i][d] = 2.f * s * c;
                cs[i][d] = 1.f - 2.f * s * s;   // cos(2a) = 1 - 2 sin^2(a)
            }
        }
        sts8(xr + 16, e4v.x, e4v.y, e4v.z, e4v.w, bx, by, bz, sn[0][0]);
        sts8(xr + 24, sn[0][1], sn[0][2], cs[0][0], cs[0][1], cs[0][2], sn[1][0], sn[1][1], sn[1][2]);
        sts8(xr + 32, cs[1][0], cs[1][1], cs[1][2], sn[2][0], sn[2][1], sn[2][2], cs[2][0], cs[2][1]);
        sts8(xr + 40, cs[2][2], sn[3][0], sn[3][1], sn[3][2], cs[3][0], cs[3][1], cs[3][2], sn[4][0]);
        sts8(xr + 48, sn[4][1], sn[4][2], cs[4][0], cs[4][1], cs[4][2], sn[5][0], sn[5][1], sn[5][2]);
        sts8(xr + 56, cs[5][0], cs[5][1], cs[5][2], sn[6][0], sn[6][1], sn[6][2], cs[6][0], cs[6][1]);

        float n0 = normals[row * 2 + 0], n1 = normals[row * 2 + 1];
        sts8(xr + 64, cs[6][2], sn[7][0], sn[7][1], sn[7][2], cs[7][0], cs[7][1], cs[7][2], n0);

        // one-blob via geometric recurrence (MUFU 32 -> 4):
        // E_k = exp(-50 (n - k/15)^2); E_{k+1} = E_k * r_k; r_0 = exp(100Δn)·exp(-50Δ²); r_{k+1} = r_k·exp(-100Δ²)
        float bl0[16], bl1[16];
        {
            const float V1 = 0.80073740291680f;   // exp(-50/225)
            const float V2 = 0.64118038843357f;   // exp(-100/225)
            float E0 = __expf(-50.f * n0 * n0);
            float r0 = __expf(6.66666667f * n0) * V1;
            float E1 = __expf(-50.f * n1 * n1);
            float r1 = __expf(6.66666667f * n1) * V1;
            bl0[0] = E0; bl1[0] = E1;
            #pragma unroll
            for (int k = 1; k < 16; k++) {
                E0 *= r0; r0 *= V2; bl0[k] = E0;
                E1 *= r1; r1 *= V2; bl1[k] = E1;
            }
        }
        sts8(xr + 72,  n1, bl0[0], bl0[1], bl0[2], bl0[3], bl0[4], bl0[5], bl0[6]);
        sts8(xr + 80,  bl0[7], bl0[8], bl0[9], bl0[10], bl0[11], bl0[12], bl0[13], bl0[14]);
        sts8(xr + 88,  bl0[15], bl1[0], bl1[1], bl1[2], bl1[3], bl1[4], bl1[5], bl1[6]);
        sts8(xr + 96,  bl1[7], bl1[8], bl1[9], bl1[10], bl1[11], bl1[12], bl1[13], bl1[14]);
        sts8(xr + 104, bl1[15], 0.f, 0.f, 0.f, 0.f, 0.f, 0.f, 0.f);  // K-pad 105..111

        __syncwarp();   // warp reads only its own 32 rows

        // ================= layer 1: [32 x 112] @ [112 x 64], K=7 steps =================
        float acc[2][8][4];
        #pragma unroll
        for (int mt = 0; mt < 2; mt++)
            #pragma unroll
            for (int nt = 0; nt < 8; nt++)
                #pragma unroll
                for (int j = 0; j < 4; j++) acc[mt][nt][j] = 0.f;

        #pragma unroll
        for (int kk = 0; kk < 7; kk++) {
            uint32_t aA[4], aB[4];
            ldsm4(aA, baseA0 + kk * 32);
            ldsm4(aB, baseA1 + kk * 32);
            #pragma unroll
            for (int p = 0; p < 4; p++) {
                uint32_t b[4];
                ldsm4(b, baseB1[p] + kk * 32);
                mma16816(acc[0][2 * p],     aA[0], aA[1], aA[2], aA[3], b[0], b[1]);
                mma16816(acc[0][2 * p + 1], aA[0], aA[1], aA[2], aA[3], b[2], b[3]);
                mma16816(acc[1][2 * p],     aB[0], aB[1], aB[2], aB[3], b[0], b[1]);
                mma16816(acc[1][2 * p + 1], aB[0], aB[1], aB[2], aB[3], b[2], b[3]);
            }
        }

        // bias + sin + pack into layer-2 A fragments (C-frag layout == A-frag layout)
        uint32_t ah[2][8][2];
        #pragma unroll
        for (int mt = 0; mt < 2; mt++)
            #pragma unroll
            for (int nt = 0; nt < 8; nt++) {
                float bv0 = B1S[nt * 8 + tig * 2];
                float bv1 = B1S[nt * 8 + tig * 2 + 1];
                ah[mt][nt][0] = pk(__sinf(acc[mt][nt][0] + bv0), __sinf(acc[mt][nt][1] + bv1));
                ah[mt][nt][1] = pk(__sinf(acc[mt][nt][2] + bv0), __sinf(acc[mt][nt][3] + bv1));
            }

        // ================= layer 2: [32 x 64] @ [64 x 64], K=4 steps (A in regs) =================
        float ac2[2][8][4];
        #pragma unroll
        for (int mt = 0; mt < 2; mt++)
            #pragma unroll
            for (int nt = 0; nt < 8; nt++)
                #pragma unroll
                for (int j = 0; j < 4; j++) ac2[mt][nt][j] = 0.f;

        #pragma unroll
        for (int kk = 0; kk < 4; kk++) {
            #pragma unroll
            for (int p = 0; p < 4; p++) {
                uint32_t b[4];
                ldsm4(b, baseB2[p] + kk * 32);
                #pragma unroll
                for (int mt = 0; mt < 2; mt++) {
                    mma16816(ac2[mt][2 * p],
                             ah[mt][2 * kk][0], ah[mt][2 * kk][1],
                             ah[mt][2 * kk + 1][0], ah[mt][2 * kk + 1][1],
                             b[0], b[1]);
                    mma16816(ac2[mt][2 * p + 1],
                             ah[mt][2 * kk][0], ah[mt][2 * kk][1],
                             ah[mt][2 * kk + 1][0], ah[mt][2 * kk + 1][1],
                             b[2], b[3]);
                }
            }
        }

        // bias + sin (in place)
        #pragma unroll
        for (int mt = 0; mt < 2; mt++)
            #pragma unroll
            for (int nt = 0; nt < 8; nt++) {
                float bv0 = B2S[nt * 8 + tig * 2];
                float bv1 = B2S[nt * 8 + tig * 2 + 1];
                ac2[mt][nt][0] = __sinf(ac2[mt][nt][0] + bv0);
                ac2[mt][nt][1] = __sinf(ac2[mt][nt][1] + bv1);
                ac2[mt][nt][2] = __sinf(ac2[mt][nt][2] + bv0);
                ac2[mt][nt][3] = __sinf(ac2[mt][nt][3] + bv1);
            }

        // ================= layer 3: [32 x 64] @ [64 x 3] + residual =================
        float b3x = B3S[0], b3y = B3S[1], b3z = B3S[2];
        #pragma unroll
        for (int mt = 0; mt < 2; mt++) {
            float pA0 = 0.f, pA1 = 0.f, pA2 = 0.f;   // row g
            float pB0 = 0.f, pB1 = 0.f, pB2 = 0.f;   // row g+8
            #pragma unroll
            for (int nt = 0; nt < 8; nt++) {
                #pragma unroll
                for (int p = 0; p < 2; p++) {
                    float4 w = W3S[nt * 8 + tig * 2 + p];
                    float vA = ac2[mt][nt][p];
                    float vB = ac2[mt][nt][2 + p];
                    pA0 += vA * w.x; pA1 += vA * w.y; pA2 += vA * w.z;
                    pB0 += vB * w.x; pB1 += vB * w.y; pB2 += vB * w.z;
                }
            }
            // reduce across the 4 lanes of the group (tig dimension)
            pA0 += __shfl_xor_sync(0xffffffffu, pA0, 1); pA0 += __shfl_xor_sync(0xffffffffu, pA0, 2);
            pA1 += __shfl_xor_sync(0xffffffffu, pA1, 1); pA1 += __shfl_xor_sync(0xffffffffu, pA1, 2);
            pA2 += __shfl_xor_sync(0xffffffffu, pA2, 1); pA2 += __shfl_xor_sync(0xffffffffu, pA2, 2);
            pB0 += __shfl_xor_sync(0xffffffffu, pB0, 1); pB0 += __shfl_xor_sync(0xffffffffu, pB0, 2);
            pB1 += __shfl_xor_sync(0xffffffffu, pB1, 1); pB1 += __shfl_xor_sync(0xffffffffu, pB1, 2);
            pB2 += __shfl_xor_sync(0xffffffffu, pB2, 1); pB2 += __shfl_xor_sync(0xffffffffu, pB2, 2);

            if (tig == 0) {
                int rA = tile * 128 + warpRow + mt * 16 + g;
                out[rA * 3 + 0] = bases[rA * 3 + 0] + pA0 + b3x;
                out[rA * 3 + 1] = bases[rA * 3 + 1] + pA1 + b3y;
                out[rA * 3 + 2] = bases[rA * 3 + 2] + pA2 + b3z;
                int rB = rA + 8;
                out[rB * 3 + 0] = bases[rB * 3 + 0] + pB0 + b3x;
                out[rB * 3 + 1] = bases[rB * 3 + 1] + pB1 + b3y;
                out[rB * 3 + 2] = bases[rB * 3 + 2] + pB2 + b3z;
            }
        }
        __syncwarp();   // all lanes done reading XS before next tile overwrites it
    }
}

extern "C" void kernel_launch(void* const* d_in, const int* in_sizes, int n_in,
                              void* d_out, int out_size) {
    const float* bases   = (const float*)d_in[0];
    const float* normals = (const float*)d_in[1];
    const float* enc     = (const float*)d_in[2];
    const float* W1      = (const float*)d_in[3];
    const float* b1      = (const float*)d_in[4];
    const float* W2      = (const float*)d_in[5];
    const float* b2      = (const float*)d_in[6];
    const float* W3      = (const float*)d_in[7];
    const float* b3      = (const float*)d_in[8];
    float* out = (float*)d_out;

    cudaFuncSetAttribute(fused_encode_mlp,
                         cudaFuncAttributeMaxDynamicSharedMemorySize, SMEM_BYTES);

    // persistent: 148 SMs x 4 CTAs (smem-limited occupancy)
    fused_encode_mlp<<<592, 128, SMEM_BYTES>>>(bases, normals, enc,
                                               W1, b1, W2, b2, W3, b3, out);
}

// round 3
// speedup vs baseline: 1.1110x; 1.0025x over previous
#include <cuda_runtime.h>
#include <cuda_fp16.h>
#include <cstdint>

#define NPTS  2000000
#define TILES 15625          // 2,000,000 / 128 exactly

// dynamic shared layout (bytes)
#define XS_OFF 0             // half [128][120]   (stride 120 halfs = 240B, conflict-free for LDSM)
#define W1_OFF 30720         // half [64][120]    W1S[j][k] = W1[k][j], k padded 105->112 (zeros)
#define W2_OFF 46080         // half [64][72]     W2S[j][k] = W2[k][j]
#define W3_OFF 55296         // float4 [64]       (W3 row k, padded)
#define B1_OFF 56320         // float [64]
#define B2_OFF 56576         // float [64]
#define B3_OFF 56832         // float [4]
#define SMEM_BYTES 56848

__device__ __forceinline__ uint32_t pk(float a, float b) {
    __half2 h = __floats2half2_rn(a, b);   // low = a, high = b
    return *reinterpret_cast<uint32_t*>(&h);
}

__device__ __forceinline__ void sts8(__half* p,
    float a, float b, float c, float d, float e, float f, float g, float h) {
    uint4 u;
    u.x = pk(a, b); u.y = pk(c, d); u.z = pk(e, f); u.w = pk(g, h);
    *reinterpret_cast<uint4*>(p) = u;      // 16B aligned: row base 240B, offsets 16B
}

// D = A(16x16,f16,row) * B(16x8,f16,col) + D,  fp32 accum
__device__ __forceinline__ void mma16816(float* c,
    uint32_t a0, uint32_t a1, uint32_t a2, uint32_t a3,
    uint32_t b0, uint32_t b1) {
    asm volatile(
        "mma.sync.aligned.m16n8k16.row.col.f32.f16.f16.f32 "
        "{%0,%1,%2,%3}, {%4,%5,%6,%7}, {%8,%9}, {%0,%1,%2,%3};\n"
        : "+f"(c[0]), "+f"(c[1]), "+f"(c[2]), "+f"(c[3])
        : "r"(a0), "r"(a1), "r"(a2), "r"(a3), "r"(b0), "r"(b1));
}

__device__ __forceinline__ void ldsm4(uint32_t* r, uint32_t addr) {
    asm volatile(
        "ldmatrix.sync.aligned.m8n8.x4.shared.b16 {%0,%1,%2,%3}, [%4];\n"
        : "=r"(r[0]), "=r"(r[1]), "=r"(r[2]), "=r"(r[3]) : "r"(addr));
}

__global__ void __launch_bounds__(128, 4)
fused_encode_mlp(const float* __restrict__ bases,
                 const float* __restrict__ normals,
                 const float* __restrict__ enc,
                 const float* __restrict__ W1, const float* __restrict__ b1,
                 const float* __restrict__ W2, const float* __restrict__ b2,
                 const float* __restrict__ W3, const float* __restrict__ b3,
                 float* __restrict__ out)
{
    extern __shared__ char smem[];
    __half*  XS  = reinterpret_cast<__half*>(smem + XS_OFF);
    __half*  W1S = reinterpret_cast<__half*>(smem + W1_OFF);
    __half*  W2S = reinterpret_cast<__half*>(smem + W2_OFF);
    float4*  W3S = reinterpret_cast<float4*>(smem + W3_OFF);
    float*   B1S = reinterpret_cast<float*>(smem + B1_OFF);
    float*   B2S = reinterpret_cast<float*>(smem + B2_OFF);
    float*   B3S = reinterpret_cast<float*>(smem + B3_OFF);

    const int tid  = threadIdx.x;
    const int lane = tid & 31;
    const int wp   = tid >> 5;
    const int g    = lane >> 2;      // groupID (row within 8)
    const int tig  = lane & 3;       // thread-in-group
    const int warpRow = wp * 32;

    // ---- stage weights once per CTA ----
    for (int i = tid; i < 64 * 120; i += 128) W1S[i] = __float2half(0.f);  // zero incl. K-pad
    __syncthreads();
    for (int i = tid; i < 105 * 64; i += 128) {
        int k = i >> 6, j = i & 63;
        W1S[j * 120 + k] = __float2half(W1[i]);
    }
    for (int i = tid; i < 64 * 64; i += 128) {
        int k = i >> 6, j = i & 63;
        W2S[j * 72 + k] = __float2half(W2[i]);
    }
    if (tid < 64) {
        W3S[tid] = make_float4(W3[tid * 3 + 0], W3[tid * 3 + 1], W3[tid * 3 + 2], 0.f);
        B1S[tid] = b1[tid];
        B2S[tid] = b2[tid];
    }
    if (tid < 3) B3S[tid] = b3[tid];
    __syncthreads();

    // ---- precompute ldmatrix base addresses (byte offsets in shared space) ----
    const uint32_t xs_b  = (uint32_t)__cvta_generic_to_shared(XS);
    const uint32_t w1_b  = (uint32_t)__cvta_generic_to_shared(W1S);
    const uint32_t w2_b  = (uint32_t)__cvta_generic_to_shared(W2S);

    // A-tile (m16 x k16) x4 lanes mapping
    const int aRowIn = (lane & 7) + ((lane >> 3) & 1) * 8;
    const int aCol   = ((lane >> 4) & 1) * 16;
    uint32_t baseA0 = xs_b + (uint32_t)((warpRow + aRowIn) * 240 + aCol);
    uint32_t baseA1 = baseA0 + 16u * 240u;

    // B-pair (two n8 x k16 tiles) mapping
    const int bRowIn = (lane & 7) + ((lane >> 4) & 1) * 8;
    const int bCol   = ((lane >> 3) & 1) * 16;
    uint32_t baseB1[4], baseB2[4];
    #pragma unroll
    for (int p = 0; p < 4; p++) {
        baseB1[p] = w1_b + (uint32_t)((p * 16 + bRowIn) * 240 + bCol);
        baseB2[p] = w2_b + (uint32_t)((p * 16 + bRowIn) * 144 + bCol);
    }

    // ---- prefetch registers (next tile's global inputs) ----
    float4 Pe0, Pe1, Pe2, Pe3, Pe4;
    float  Pbx, Pby, Pbz, Pn0, Pn1;

    // preload first tile
    {
        const int row = blockIdx.x * 128 + tid;
        const float4* ep = reinterpret_cast<const float4*>(enc + (size_t)row * 20);
        Pe0 = ep[0]; Pe1 = ep[1]; Pe2 = ep[2]; Pe3 = ep[3]; Pe4 = ep[4];
        Pbx = bases[row * 3 + 0]; Pby = bases[row * 3 + 1]; Pbz = bases[row * 3 + 2];
        Pn0 = normals[row * 2 + 0]; Pn1 = normals[row * 2 + 1];
    }

    for (int tile = blockIdx.x; tile < TILES; tile += gridDim.x) {
        // consume prefetched inputs
        float4 e0 = Pe0, e1 = Pe1, e2 = Pe2, e3 = Pe3, e4v = Pe4;
        float bx = Pbx, by = Pby, bz = Pbz, n0 = Pn0, n1 = Pn1;

        // ================= features -> SMEM (fp16, cols 0..111) =================
        __half* xr = XS + tid * 120;

        sts8(xr + 0, e0.x, e0.y, e0.z, e0.w, e1.x, e1.y, e1.z, e1.w);
        sts8(xr + 8, e2.x, e2.y, e2.z, e2.w, e3.x, e3.y, e3.z, e3.w);

        // posenc via double-angle recurrence: one sincos per dim
        float sn[8][3], cs[8][3];
        __sincosf(2.f * bx, &sn[0][0], &cs[0][0]);
        __sincosf(2.f * by, &sn[0][1], &cs[0][1]);
        __sincosf(2.f * bz, &sn[0][2], &cs[0][2]);
        #pragma unroll
        for (int i = 1; i < 8; i++) {
            #pragma unroll
            for (int d = 0; d < 3; d++) {
                float s = sn[i - 1][d], c = cs[i - 1][d];
                sn[i][d] = 2.f * s * c;
                cs[i][d] = 1.f - 2.f * s * s;   // cos(2a) = 1 - 2 sin^2(a)
            }
        }
        sts8(xr + 16, e4v.x, e4v.y, e4v.z, e4v.w, bx, by, bz, sn[0][0]);
        sts8(xr + 24, sn[0][1], sn[0][2], cs[0][0], cs[0][1], cs[0][2], sn[1][0], sn[1][1], sn[1][2]);
        sts8(xr + 32, cs[1][0], cs[1][1], cs[1][2], sn[2][0], sn[2][1], sn[2][2], cs[2][0], cs[2][1]);
        sts8(xr + 40, cs[2][2], sn[3][0], sn[3][1], sn[3][2], cs[3][0], cs[3][1], cs[3][2], sn[4][0]);
        sts8(xr + 48, sn[4][1], sn[4][2], cs[4][0], cs[4][1], cs[4][2], sn[5][0], sn[5][1], sn[5][2]);
        sts8(xr + 56, cs[5][0], cs[5][1], cs[5][2], sn[6][0], sn[6][1], sn[6][2], cs[6][0], cs[6][1]);
        sts8(xr + 64, cs[6][2], sn[7][0], sn[7][1], sn[7][2], cs[7][0], cs[7][1], cs[7][2], n0);

        // one-blob via geometric recurrence
        float bl0[16], bl1[16];
        {
            const float V1 = 0.80073740291680f;   // exp(-50/225)
            const float V2 = 0.64118038843357f;   // exp(-100/225)
            float E0 = __expf(-50.f * n0 * n0);
            float r0 = __expf(6.66666667f * n0) * V1;
            float E1 = __expf(-50.f * n1 * n1);
            float r1 = __expf(6.66666667f * n1) * V1;
            bl0[0] = E0; bl1[0] = E1;
            #pragma unroll
            for (int k = 1; k < 16; k++) {
                E0 *= r0; r0 *= V2; bl0[k] = E0;
                E1 *= r1; r1 *= V2; bl1[k] = E1;
            }
        }
        sts8(xr + 72,  n1, bl0[0], bl0[1], bl0[2], bl0[3], bl0[4], bl0[5], bl0[6]);
        sts8(xr + 80,  bl0[7], bl0[8], bl0[9], bl0[10], bl0[11], bl0[12], bl0[13], bl0[14]);
        sts8(xr + 88,  bl0[15], bl1[0], bl1[1], bl1[2], bl1[3], bl1[4], bl1[5], bl1[6]);
        sts8(xr + 96,  bl1[7], bl1[8], bl1[9], bl1[10], bl1[11], bl1[12], bl1[13], bl1[14]);
        sts8(xr + 104, bl1[15], 0.f, 0.f, 0.f, 0.f, 0.f, 0.f, 0.f);  // K-pad 105..111

        // ---- issue next tile's global loads NOW; MMA section hides the latency ----
        {
            int nt = tile + gridDim.x;
            if (nt >= TILES) nt = TILES - 1;            // clamp: always valid, deterministic
            const int prow = nt * 128 + tid;
            const float4* ep = reinterpret_cast<const float4*>(enc + (size_t)prow * 20);
            Pe0 = ep[0]; Pe1 = ep[1]; Pe2 = ep[2]; Pe3 = ep[3]; Pe4 = ep[4];
            Pbx = bases[prow * 3 + 0]; Pby = bases[prow * 3 + 1]; Pbz = bases[prow * 3 + 2];
            Pn0 = normals[prow * 2 + 0]; Pn1 = normals[prow * 2 + 1];
        }

        __syncwarp();   // warp reads only its own 32 rows

        // ================= layer 1: [32 x 112] @ [112 x 64], K=7 steps =================
        float acc[2][8][4];
        #pragma unroll
        for (int mt = 0; mt < 2; mt++)
            #pragma unroll
            for (int nt = 0; nt < 8; nt++)
                #pragma unroll
                for (int j = 0; j < 4; j++) acc[mt][nt][j] = 0.f;

        #pragma unroll
        for (int kk = 0; kk < 7; kk++) {
            uint32_t aA[4], aB[4];
            ldsm4(aA, baseA0 + kk * 32);
            ldsm4(aB, baseA1 + kk * 32);
            #pragma unroll
            for (int p = 0; p < 4; p++) {
                uint32_t b[4];
                ldsm4(b, baseB1[p] + kk * 32);
                mma16816(acc[0][2 * p],     aA[0], aA[1], aA[2], aA[3], b[0], b[1]);
                mma16816(acc[0][2 * p + 1], aA[0], aA[1], aA[2], aA[3], b[2], b[3]);
                mma16816(acc[1][2 * p],     aB[0], aB[1], aB[2], aB[3], b[0], b[1]);
                mma16816(acc[1][2 * p + 1], aB[0], aB[1], aB[2], aB[3], b[2], b[3]);
            }
        }

        // bias + sin + pack into layer-2 A fragments (C-frag layout == A-frag layout)
        uint32_t ah[2][8][2];
        #pragma unroll
        for (int mt = 0; mt < 2; mt++)
            #pragma unroll
            for (int nt = 0; nt < 8; nt++) {
                float bv0 = B1S[nt * 8 + tig * 2];
                float bv1 = B1S[nt * 8 + tig * 2 + 1];
                ah[mt][nt][0] = pk(__sinf(acc[mt][nt][0] + bv0), __sinf(acc[mt][nt][1] + bv1));
                ah[mt][nt][1] = pk(__sinf(acc[mt][nt][2] + bv0), __sinf(acc[mt][nt][3] + bv1));
            }

        // ================= layer 2: [32 x 64] @ [64 x 64], K=4 steps (A in regs) =================
        float ac2[2][8][4];
        #pragma unroll
        for (int mt = 0; mt < 2; mt++)
            #pragma unroll
            for (int nt = 0; nt < 8; nt++)
                #pragma unroll
                for (int j = 0; j < 4; j++) ac2[mt][nt][j] = 0.f;

        #pragma unroll
        for (int kk = 0; kk < 4; kk++) {
            #pragma unroll
            for (int p = 0; p < 4; p++) {
                uint32_t b[4];
                ldsm4(b, baseB2[p] + kk * 32);
                #pragma unroll
                for (int mt = 0; mt < 2; mt++) {
                    mma16816(ac2[mt][2 * p],
                             ah[mt][2 * kk][0], ah[mt][2 * kk][1],
                             ah[mt][2 * kk + 1][0], ah[mt][2 * kk + 1][1],
                             b[0], b[1]);
                    mma16816(ac2[mt][2 * p + 1],
                             ah[mt][2 * kk][0], ah[mt][2 * kk][1],
                             ah[mt][2 * kk + 1][0], ah[mt][2 * kk + 1][1],
                             b[2], b[3]);
                }
            }
        }

        // bias + sin (in place)
        #pragma unroll
        for (int mt = 0; mt < 2; mt++)
            #pragma unroll
            for (int nt = 0; nt < 8; nt++) {
                float bv0 = B2S[nt * 8 + tig * 2];
                float bv1 = B2S[nt * 8 + tig * 2 + 1];
                ac2[mt][nt][0] = __sinf(ac2[mt][nt][0] + bv0);
                ac2[mt][nt][1] = __sinf(ac2[mt][nt][1] + bv1);
                ac2[mt][nt][2] = __sinf(ac2[mt][nt][2] + bv0);
                ac2[mt][nt][3] = __sinf(ac2[mt][nt][3] + bv1);
            }

        // ================= layer 3: [32 x 64] @ [64 x 3] + residual =================
        float b3x = B3S[0], b3y = B3S[1], b3z = B3S[2];
        #pragma unroll
        for (int mt = 0; mt < 2; mt++) {
            float pA0 = 0.f, pA1 = 0.f, pA2 = 0.f;   // row g
            float pB0 = 0.f, pB1 = 0.f, pB2 = 0.f;   // row g+8
            #pragma unroll
            for (int nt = 0; nt < 8; nt++) {
                #pragma unroll
                for (int p = 0; p < 2; p++) {
                    float4 w = W3S[nt * 8 + tig * 2 + p];
                    float vA = ac2[mt][nt][p];
                    float vB = ac2[mt][nt][2 + p];
                    pA0 += vA * w.x; pA1 += vA * w.y; pA2 += vA * w.z;
                    pB0 += vB * w.x; pB1 += vB * w.y; pB2 += vB * w.z;
                }
            }
            // reduce across the 4 lanes of the group (tig dimension)
            pA0 += __shfl_xor_sync(0xffffffffu, pA0, 1); pA0 += __shfl_xor_sync(0xffffffffu, pA0, 2);
            pA1 += __shfl_xor_sync(0xffffffffu, pA1, 1); pA1 += __shfl_xor_sync(0xffffffffu, pA1, 2);
            pA2 += __shfl_xor_sync(0xffffffffu, pA2, 1); pA2 += __shfl_xor_sync(0xffffffffu, pA2, 2);
            pB0 += __shfl_xor_sync(0xffffffffu, pB0, 1); pB0 += __shfl_xor_sync(0xffffffffu, pB0, 2);
            pB1 += __shfl_xor_sync(0xffffffffu, pB1, 1); pB1 += __shfl_xor_sync(0xffffffffu, pB1, 2);
            pB2 += __shfl_xor_sync(0xffffffffu, pB2, 1); pB2 += __shfl_xor_sync(0xffffffffu, pB2, 2);

            if (tig == 0) {
                int rA = tile * 128 + warpRow + mt * 16 + g;
                out[rA * 3 + 0] = bases[rA * 3 + 0] + pA0 + b3x;
                out[rA * 3 + 1] = bases[rA * 3 + 1] + pA1 + b3y;
                out[rA * 3 + 2] = bases[rA * 3 + 2] + pA2 + b3z;
                int rB = rA + 8;
                out[rB * 3 + 0] = bases[rB * 3 + 0] + pB0 + b3x;
                out[rB * 3 + 1] = bases[rB * 3 + 1] + pB1 + b3y;
                out[rB * 3 + 2] = bases[rB * 3 + 2] + pB2 + b3z;
            }
        }
        __syncwarp();   // all lanes done reading XS before next tile overwrites it
    }
}

extern "C" void kernel_launch(void* const* d_in, const int* in_sizes, int n_in,
                              void* d_out, int out_size) {
    const float* bases   = (const float*)d_in[0];
    const float* normals = (const float*)d_in[1];
    const float* enc     = (const float*)d_in[2];
    const float* W1      = (const float*)d_in[3];
    const float* b1      = (const float*)d_in[4];
    const float* W2      = (const float*)d_in[5];
    const float* b2      = (const float*)d_in[6];
    const float* W3      = (const float*)d_in[7];
    const float* b3      = (const float*)d_in[8];
    float* out = (float*)d_out;

    cudaFuncSetAttribute(fused_encode_mlp,
                         cudaFuncAttributeMaxDynamicSharedMemorySize, SMEM_BYTES);

    // persistent: 148 SMs x 4 CTAs (smem-limited occupancy)
    fused_encode_mlp<<<592, 128, SMEM_BYTES>>>(bases, normals, enc,
                                               W1, b1, W2, b2, W3, b3, out);
}